// round 16
// baseline (speedup 1.0000x reference)
#include <cuda_runtime.h>
#include <cuda_bf16.h>
#include <stdint.h>

// Problem constants
#define S_ 2048
#define D_ 1024
#define HN 16
#define DK 64
#define BH 32
#define MR 4096                      // B*S
#define OUT_OFF ((size_t)MR*D_)      // start of attention_weights in d_out

// Scratch (device globals — referenced ONLY in device code)
__device__ float g_v[BH*S_*DK];                    // [bh][s][dk] fp32 (pre-transpose)
__device__ __nv_bfloat16 g_qh[BH*S_*DK], g_ql[BH*S_*DK];   // [bh][s][dk]
__device__ __nv_bfloat16 g_kh[BH*S_*DK], g_kl[BH*S_*DK];
__device__ __nv_bfloat16 g_vth[BH*DK*S_], g_vtl[BH*DK*S_]; // [bh][dk][s]
__device__ __nv_bfloat16 g_xh[(size_t)3*MR*D_], g_xl[(size_t)3*MR*D_];   // split inputs
__device__ __nv_bfloat16 g_wth[(size_t)4*D_*D_], g_wtl[(size_t)4*D_*D_]; // W^T hi/lo
__device__ __nv_bfloat16 g_ctxh[(size_t)MR*D_], g_ctxl[(size_t)MR*D_];
__device__ float2 g_stats[(size_t)BH*S_*16];       // per (row, n-tile): (max, sumexp)
__device__ float g_tilescale[(size_t)BH*S_*16];    // per (row, n-tile): exp(m_t-m)/s

// ---------------------------------------------------------------------------
// Helpers
// ---------------------------------------------------------------------------
__device__ __forceinline__ uint32_t smem_u32(const void* p) {
    uint32_t a;
    asm("{ .reg .u64 t; cvta.to.shared.u64 t, %1; cvt.u32.u64 %0, t; }" : "=r"(a) : "l"(p));
    return a;
}
__device__ __forceinline__ void ldmx4(uint32_t& r0, uint32_t& r1, uint32_t& r2,
                                      uint32_t& r3, uint32_t addr) {
    asm volatile("ldmatrix.sync.aligned.m8n8.x4.shared.b16 {%0,%1,%2,%3}, [%4];"
                 : "=r"(r0), "=r"(r1), "=r"(r2), "=r"(r3) : "r"(addr));
}
__device__ __forceinline__ void mma16816(float* c, const uint32_t* a, const uint32_t* b) {
    asm volatile("mma.sync.aligned.m16n8k16.row.col.f32.bf16.bf16.f32 "
                 "{%0,%1,%2,%3}, {%4,%5,%6,%7}, {%8,%9}, {%0,%1,%2,%3};"
                 : "+f"(c[0]), "+f"(c[1]), "+f"(c[2]), "+f"(c[3])
                 : "r"(a[0]), "r"(a[1]), "r"(a[2]), "r"(a[3]), "r"(b[0]), "r"(b[1]));
}
#define CPA16(dst, src) \
    asm volatile("cp.async.cg.shared.global [%0], [%1], 16;" :: "r"(dst), "l"(src) : "memory")
#define CPA_COMMIT() asm volatile("cp.async.commit_group;" ::: "memory")
#define CPA_WAIT(n)  asm volatile("cp.async.wait_group %0;" :: "n"(n) : "memory")

// Streaming (evict-first) global accessors for single-touch 536MB streams
__device__ __forceinline__ float4 ldcs4(const float* p) {
    float4 v;
    asm volatile("ld.global.cs.v4.f32 {%0,%1,%2,%3}, [%4];"
                 : "=f"(v.x), "=f"(v.y), "=f"(v.z), "=f"(v.w) : "l"(p));
    return v;
}
__device__ __forceinline__ void stcs4(float* p, float4 v) {
    asm volatile("st.global.cs.v4.f32 [%0], {%1,%2,%3,%4};"
                 :: "l"(p), "f"(v.x), "f"(v.y), "f"(v.z), "f"(v.w) : "memory");
}
__device__ __forceinline__ void stcs2(float* p, float2 v) {
    asm volatile("st.global.cs.v2.f32 [%0], {%1,%2};"
                 :: "l"(p), "f"(v.x), "f"(v.y) : "memory");
}

// Split two fp32 into packed-bf16x2 (hi) and packed-bf16x2 residual (lo)
__device__ __forceinline__ void split2(float x, float y, uint32_t& hi, uint32_t& lo) {
    __nv_bfloat162 h2 = __float22bfloat162_rn(make_float2(x, y));
    uint32_t hb = *reinterpret_cast<uint32_t*>(&h2);
    float hx = __uint_as_float(hb << 16);
    float hy = __uint_as_float(hb & 0xFFFF0000u);
    __nv_bfloat162 l2 = __float22bfloat162_rn(make_float2(x - hx, y - hy));
    hi = hb;
    lo = *reinterpret_cast<uint32_t*>(&l2);
}
__device__ __forceinline__ void st_pair(__nv_bfloat16* dh, __nv_bfloat16* dl,
                                        size_t off, float v0, float v1) {
    uint32_t h, l; split2(v0, v1, h, l);
    *(uint32_t*)(dh + off) = h;
    *(uint32_t*)(dl + off) = l;
}
// Swizzled byte offset within a [rows x 32 bf16] region (64B rows, 16B chunks)
__device__ __forceinline__ uint32_t swo(int r, int cc) {
    return (uint32_t)(r * 64 + ((cc ^ ((r >> 1) & 3)) * 16));
}

// ---------------------------------------------------------------------------
// Merged elementwise split: grid (MR*D_/1024, 3); slot = blockIdx.y
// ---------------------------------------------------------------------------
__global__ void split3_kernel(const float* __restrict__ s0,
                              const float* __restrict__ s1,
                              const float* __restrict__ s2)
{
    int slot = blockIdx.y;
    const float* src = slot == 0 ? s0 : slot == 1 ? s1 : s2;
    __nv_bfloat16* dh = g_xh + (size_t)slot * MR * D_;
    __nv_bfloat16* dl = g_xl + (size_t)slot * MR * D_;
    size_t i = ((size_t)blockIdx.x * blockDim.x + threadIdx.x) * 4;
    float4 v = *(const float4*)(src + i);
    uint32_t h0, l0, h1, l1;
    split2(v.x, v.y, h0, l0);
    split2(v.z, v.w, h1, l1);
    *(uint2*)(dh + i) = make_uint2(h0, h1);
    *(uint2*)(dl + i) = make_uint2(l0, l1);
}

// ---------------------------------------------------------------------------
// Merged weight transpose+split: grid (32,32,4); dsel = blockIdx.z
// ---------------------------------------------------------------------------
__global__ void wt4_transpose_kernel(const float* __restrict__ w0,
                                     const float* __restrict__ w1,
                                     const float* __restrict__ w2,
                                     const float* __restrict__ w3)
{
    __shared__ float t[32][33];
    int dsel = blockIdx.z;
    const float* s = dsel == 0 ? w0 : dsel == 1 ? w1 : dsel == 2 ? w2 : w3;
    __nv_bfloat16* oh = g_wth + (size_t)dsel * D_ * D_;
    __nv_bfloat16* ol = g_wtl + (size_t)dsel * D_ * D_;
    int r0 = blockIdx.y * 32, c0 = blockIdx.x * 32;
    int x = threadIdx.x, y = threadIdx.y;
    #pragma unroll
    for (int i = 0; i < 32; i += 8)
        t[y + i][x] = s[(size_t)(r0 + y + i) * D_ + c0 + x];
    __syncthreads();
    #pragma unroll
    for (int i = 0; i < 32; i += 8) {
        float v = t[x][y + i];
        __nv_bfloat16 hb = __float2bfloat16(v);
        float r = v - __bfloat162float(hb);
        size_t o = (size_t)(c0 + y + i) * D_ + r0 + x;
        oh[o] = hb;
        ol[o] = __float2bfloat16(r);
    }
}

// ---------------------------------------------------------------------------
// V transpose+split per head: g_vt*[bh][dk][s] = split(g_v[bh][s][dk])
// grid (DK/32, S_/32, BH), block (32,8)
// ---------------------------------------------------------------------------
__global__ void vt_transpose_kernel()
{
    __shared__ float t[32][33];
    const float* s = g_v + (size_t)blockIdx.z * S_ * DK;
    __nv_bfloat16* oh = g_vth + (size_t)blockIdx.z * DK * S_;
    __nv_bfloat16* ol = g_vtl + (size_t)blockIdx.z * DK * S_;
    int r0 = blockIdx.y * 32, c0 = blockIdx.x * 32;
    int x = threadIdx.x, y = threadIdx.y;
    #pragma unroll
    for (int i = 0; i < 32; i += 8)
        t[y + i][x] = s[(size_t)(r0 + y + i) * DK + c0 + x];
    __syncthreads();
    #pragma unroll
    for (int i = 0; i < 32; i += 8) {
        float v = t[x][y + i];
        __nv_bfloat16 hb = __float2bfloat16(v);
        float r = v - __bfloat162float(hb);
        size_t o = (size_t)(c0 + y + i) * S_ + r0 + x;
        oh[o] = hb;
        ol[o] = __float2bfloat16(r);
    }
}

// ---------------------------------------------------------------------------
// MMA block: NT n-tiles/warp. A-hi at bbA, A-lo at bbA+ALO.
// B-hi at bbB, B-lo at bbB+BLO. Accumulates into c[2][NT][4].
// ---------------------------------------------------------------------------
#define MMA_BLOCK(NT, bbA, ALO, bbB, BLO)                                       \
    do {                                                                        \
        _Pragma("unroll")                                                       \
        for (int ks = 0; ks < 2; ks++) {                                        \
            uint32_t ah[2][4], al[2][4], bhf[NT][2], blf[NT][2];                \
            const int cc = ks * 2 + (lane >> 4);                                \
            _Pragma("unroll")                                                   \
            for (int i = 0; i < 2; i++) {                                       \
                int r = wm * 32 + i * 16 + (lane & 15);                         \
                uint32_t o = swo(r, cc);                                        \
                ldmx4(ah[i][0], ah[i][1], ah[i][2], ah[i][3], (bbA) + o);       \
                ldmx4(al[i][0], al[i][1], al[i][2], al[i][3], (bbA) + (ALO) + o);\
            }                                                                   \
            _Pragma("unroll")                                                   \
            for (int g = 0; g < NT / 2; g++) {                                  \
                int r = wn * (NT * 8) + g * 16 + (lane & 15);                   \
                uint32_t o = swo(r, cc);                                        \
                uint32_t t0, t1, t2, t3;                                        \
                ldmx4(t0, t1, t2, t3, (bbB) + o);                               \
                bhf[2*g][0] = t0; bhf[2*g+1][0] = t1;                           \
                bhf[2*g][1] = t2; bhf[2*g+1][1] = t3;                           \
                ldmx4(t0, t1, t2, t3, (bbB) + (BLO) + o);                       \
                blf[2*g][0] = t0; blf[2*g+1][0] = t1;                           \
                blf[2*g][1] = t2; blf[2*g+1][1] = t3;                           \
            }                                                                   \
            _Pragma("unroll")                                                   \
            for (int i = 0; i < 2; i++)                                         \
                _Pragma("unroll")                                               \
                for (int j = 0; j < NT; j++) {                                  \
                    mma16816(c[i][j], ah[i], bhf[j]);                           \
                    mma16816(c[i][j], ah[i], blf[j]);                           \
                    mma16816(c[i][j], al[i], bhf[j]);                           \
                }                                                               \
        }                                                                       \
    } while (0)

// ---------------------------------------------------------------------------
// gemm_ps<MODE>: pre-split A,B (bf16 hi/lo, LD=1024, K=1024), tile 128x128.
// MODE 0: sel=blockIdx.z: A=g_x[sel], B=g_wt[sel] -> q/k bf16 pairs or v fp32
// MODE 1: A=g_ctx, B=g_wt[3] -> d_out fp32 + bias
// smem: 3 stages x 32KB {AH 8K | AL 8K | BH 8K | BL 8K}; 1 sync/chunk
// ---------------------------------------------------------------------------
template <int MODE>
__global__ __launch_bounds__(256)
void gemm_ps(const float* __restrict__ b0, const float* __restrict__ b1,
             const float* __restrict__ b2, float* __restrict__ Cext)
{
    constexpr int NC = 32;
    extern __shared__ char sm[];
    const uint32_t smb = smem_u32(sm);
    const int tid = threadIdx.x, lane = tid & 31, wid = tid >> 5;
    const int wm = wid & 3, wn = wid >> 2;
    const int m0 = blockIdx.y * 128;
    const int n0 = blockIdx.x * 128;
    const int sel = (MODE == 0) ? blockIdx.z : 3;
    const float* bias = (MODE == 0) ? (sel == 0 ? b0 : sel == 1 ? b1 : b2) : b0;

    const __nv_bfloat16 *Ah, *Al, *Bh, *Bl;
    if (MODE == 0) {
        Ah = g_xh + (size_t)sel * MR * D_;  Al = g_xl + (size_t)sel * MR * D_;
    } else {
        Ah = g_ctxh;                        Al = g_ctxl;
    }
    Bh = g_wth + (size_t)sel * D_ * D_;     Bl = g_wtl + (size_t)sel * D_ * D_;
    Ah += (size_t)m0 * D_; Al += (size_t)m0 * D_;
    Bh += (size_t)n0 * D_; Bl += (size_t)n0 * D_;

    float c[2][8][4] = {};

#define ISSUE_PS(buf, ch) do {                                                  \
    uint32_t base = smb + (uint32_t)(buf) * 32768;                              \
    int k0 = (ch) * 32;                                                         \
    _Pragma("unroll")                                                           \
    for (int t = 0; t < 2; t++) {                                               \
        int id = tid + t * 256; int r = id >> 2, cc = id & 3;                   \
        uint32_t o = swo(r, cc);                                                \
        size_t go = (size_t)r * D_ + k0 + cc * 8;                               \
        CPA16(base + o,         Ah + go);                                       \
        CPA16(base + 8192 + o,  Al + go);                                       \
        CPA16(base + 16384 + o, Bh + go);                                       \
        CPA16(base + 24576 + o, Bl + go);                                       \
    }                                                                           \
    CPA_COMMIT();                                                               \
} while (0)

    ISSUE_PS(0, 0);
    ISSUE_PS(1, 1);
    int buf = 0;
    for (int ch = 0; ch < NC; ch++) {
        if (ch + 1 < NC) { CPA_WAIT(1); } else { CPA_WAIT(0); }
        __syncthreads();
        const uint32_t bb = smb + (uint32_t)buf * 32768;
        MMA_BLOCK(8, bb, 8192, bb + 16384, 8192);
        if (ch + 2 < NC) {
            int nbuf = buf + 2; if (nbuf >= 3) nbuf -= 3;
            ISSUE_PS(nbuf, ch + 2);
        }
        if (++buf == 3) buf = 0;
    }
#undef ISSUE_PS

    // Epilogue
    const int mr0 = m0 + wm * 32 + (lane >> 2);
    const int nl0 = wn * 64 + 2 * (lane & 3);
    #pragma unroll
    for (int i = 0; i < 2; i++)
        #pragma unroll
        for (int j = 0; j < 8; j++) {
            int n_loc = nl0 + j * 8;
            int ng = n0 + n_loc;
            float2 bv = *(const float2*)(bias + ng);
            #pragma unroll
            for (int half = 0; half < 2; half++) {
                int m = mr0 + i * 16 + half * 8;
                float v0 = c[i][j][half * 2 + 0] + bv.x;
                float v1 = c[i][j][half * 2 + 1] + bv.y;
                if constexpr (MODE == 0) {
                    int h = ng >> 6, d = ng & 63;
                    int b2_ = m >> 11, s = m & (S_ - 1);
                    size_t off = (((size_t)(b2_ * HN + h)) * S_ + s) * DK + d;
                    if (sel == 0)      st_pair(g_qh, g_ql, off, v0, v1);
                    else if (sel == 1) st_pair(g_kh, g_kl, off, v0, v1);
                    else               *(float2*)(g_v + off) = make_float2(v0, v1);
                } else {
                    *(float2*)(Cext + (size_t)m * D_ + ng) = make_float2(v0, v1);
                }
            }
        }
}

// ---------------------------------------------------------------------------
// scores: x = 0.125 * Q K^T; stores e = exp(x - m_tile) (single exp, also used
// for the tile sum) + per-(row, n-tile) stats. K=64 single shot, tile 128x128.
// smem 64KB: QH [2 chunks x 8K] | QL +16384 | KH +32768 | KL +49152
// ---------------------------------------------------------------------------
__global__ __launch_bounds__(256)
void scores_mma(float* __restrict__ attn)
{
    extern __shared__ char sm[];
    __shared__ float s_max[2][128];
    __shared__ float s_sum[2][128];
    const uint32_t smb = smem_u32(sm);
    const int tid = threadIdx.x, lane = tid & 31, wid = tid >> 5;
    const int wm = wid & 3, wn = wid >> 2;
    const int m0 = blockIdx.y * 128;
    const int n0 = blockIdx.x * 128;
    const int bh = blockIdx.z;

    const __nv_bfloat16* Qh = g_qh + ((size_t)bh * S_ + m0) * DK;
    const __nv_bfloat16* Ql = g_ql + ((size_t)bh * S_ + m0) * DK;
    const __nv_bfloat16* Kh = g_kh + ((size_t)bh * S_ + n0) * DK;
    const __nv_bfloat16* Kl = g_kl + ((size_t)bh * S_ + n0) * DK;

    #pragma unroll
    for (int t = 0; t < 4; t++) {
        int id = tid + t * 256;
        int ch = id >> 9, r = (id >> 2) & 127, cc = id & 3;
        uint32_t o = (uint32_t)ch * 8192 + swo(r, cc);
        size_t go = (size_t)r * DK + ch * 32 + cc * 8;
        CPA16(smb + o,         Qh + go);
        CPA16(smb + 16384 + o, Ql + go);
        CPA16(smb + 32768 + o, Kh + go);
        CPA16(smb + 49152 + o, Kl + go);
    }
    CPA_COMMIT();
    CPA_WAIT(0);
    __syncthreads();

    float c[2][8][4] = {};
    #pragma unroll
    for (int chk = 0; chk < 2; chk++) {
        const uint32_t bb = smb + (uint32_t)chk * 8192;
        MMA_BLOCK(8, bb, 16384, bb + 32768, 16384);
    }

    // Scale into scores; per-row tile max (quad shuffles + cross-wn smem)
    #pragma unroll
    for (int i = 0; i < 2; i++)
        #pragma unroll
        for (int j = 0; j < 8; j++)
            #pragma unroll
            for (int k = 0; k < 4; k++) c[i][j][k] *= 0.125f;

    float lmax[2][2] = {{-1e30f, -1e30f}, {-1e30f, -1e30f}};
    #pragma unroll
    for (int i = 0; i < 2; i++)
        #pragma unroll
        for (int j = 0; j < 8; j++)
            #pragma unroll
            for (int half = 0; half < 2; half++)
                lmax[i][half] = fmaxf(lmax[i][half],
                                      fmaxf(c[i][j][half*2], c[i][j][half*2+1]));
    #pragma unroll
    for (int i = 0; i < 2; i++)
        #pragma unroll
        for (int half = 0; half < 2; half++) {
            float v = lmax[i][half];
            v = fmaxf(v, __shfl_xor_sync(0xffffffffu, v, 1));
            v = fmaxf(v, __shfl_xor_sync(0xffffffffu, v, 2));
            if ((lane & 3) == 0) {
                int rl = wm * 32 + (lane >> 2) + i * 16 + half * 8;
                s_max[wn][rl] = v;
            }
        }
    __syncthreads();

    // e = exp(x - m_tile); store e; accumulate tile sum
    const int mr0 = m0 + wm * 32 + (lane >> 2);
    const int nl0 = wn * 64 + 2 * (lane & 3);
    float* C = attn + (size_t)bh * S_ * S_;
    float fullm[2][2], lsum[2][2] = {};
    #pragma unroll
    for (int i = 0; i < 2; i++)
        #pragma unroll
        for (int half = 0; half < 2; half++) {
            int rl = wm * 32 + (lane >> 2) + i * 16 + half * 8;
            fullm[i][half] = fmaxf(s_max[0][rl], s_max[1][rl]);
        }
    #pragma unroll
    for (int i = 0; i < 2; i++)
        #pragma unroll
        for (int j = 0; j < 8; j++) {
            int ng = n0 + nl0 + j * 8;
            #pragma unroll
            for (int half = 0; half < 2; half++) {
                int m = mr0 + i * 16 + half * 8;
                float e0 = __expf(c[i][j][half*2]   - fullm[i][half]);
                float e1 = __expf(c[i][j][half*2+1] - fullm[i][half]);
                stcs2(C + (size_t)m * S_ + ng, make_float2(e0, e1));
                lsum[i][half] += e0 + e1;
            }
        }
    #pragma unroll
    for (int i = 0; i < 2; i++)
        #pragma unroll
        for (int half = 0; half < 2; half++) {
            float v = lsum[i][half];
            v += __shfl_xor_sync(0xffffffffu, v, 1);
            v += __shfl_xor_sync(0xffffffffu, v, 2);
            if ((lane & 3) == 0) {
                int rl = wm * 32 + (lane >> 2) + i * 16 + half * 8;
                s_sum[wn][rl] = v;
            }
        }
    __syncthreads();

    if (wn == 0 && (lane & 3) == 0) {
        #pragma unroll
        for (int i = 0; i < 2; i++)
            #pragma unroll
            for (int half = 0; half < 2; half++) {
                int rl = wm * 32 + (lane >> 2) + i * 16 + half * 8;
                g_stats[((size_t)bh * S_ + m0 + rl) * 16 + blockIdx.x] =
                    make_float2(fullm[i][half], s_sum[0][rl] + s_sum[1][rl]);
            }
    }
}

// ---------------------------------------------------------------------------
// merge_stats: per row fold 16 tile partials -> tilescale[t] = exp(m_t - m)/s
// ---------------------------------------------------------------------------
__global__ void merge_stats()
{
    size_t row = (size_t)blockIdx.x * blockDim.x + threadIdx.x;  // BH*S_ rows
    const float2* st = g_stats + row * 16;
    float2 s[16];
    #pragma unroll
    for (int t = 0; t < 16; t++) s[t] = st[t];
    float m = -1e30f;
    #pragma unroll
    for (int t = 0; t < 16; t++) m = fmaxf(m, s[t].x);
    float sum = 0.f;
    float e[16];
    #pragma unroll
    for (int t = 0; t < 16; t++) { e[t] = __expf(s[t].x - m); sum += s[t].y * e[t]; }
    float inv = 1.0f / sum;
    float* dst = g_tilescale + row * 16;
    #pragma unroll
    for (int t = 0; t < 16; t++) dst[t] = e[t] * inv;
}

// ---------------------------------------------------------------------------
// av: ctx = P @ V with P = e * tilescale (FMUL only, no exp); P written back
// in place (final attention_weights). B = pre-split V^T.
// tile 128x64, K=2048, NC=64. smem 3 stages x 24KB {AH|AL|BH|BL}; 1 sync/chunk
// ---------------------------------------------------------------------------
__global__ __launch_bounds__(256)
void av_mma(float* __restrict__ attn)
{
    constexpr int NC = 64;
    extern __shared__ char sm[];
    const uint32_t smb = smem_u32(sm);
    const int tid = threadIdx.x, lane = tid & 31, wid = tid >> 5;
    const int wm = wid & 3, wn = wid >> 2;
    const int m0 = blockIdx.y * 128;
    const int bh = blockIdx.z;

    float* Ap = attn + (size_t)bh * S_ * S_ + (size_t)m0 * S_;
    const __nv_bfloat16* Bh_ = g_vth + (size_t)bh * DK * S_;
    const __nv_bfloat16* Bl_ = g_vtl + (size_t)bh * DK * S_;
    const float* tsc = g_tilescale + ((size_t)bh * S_ + m0) * 16;

    float c[2][4][4] = {};
    float4 ra[2][2];

#define LOADA(k0) do {                                                          \
    const int tl = (k0) >> 7;                                                   \
    _Pragma("unroll")                                                           \
    for (int t = 0; t < 2; t++) {                                               \
        int id = tid + t * 256; int r = id >> 2, cc = id & 3;                   \
        float sc = tsc[(size_t)r * 16 + tl];                                    \
        float* p = Ap + (size_t)r * S_ + (k0) + cc * 8;                         \
        float4 a0 = ldcs4(p), a1 = ldcs4(p + 4);                                \
        a0.x *= sc; a0.y *= sc; a0.z *= sc; a0.w *= sc;                         \
        a1.x *= sc; a1.y *= sc; a1.z *= sc; a1.w *= sc;                         \
        stcs4(p, a0); stcs4(p + 4, a1);                                         \
        ra[t][0] = a0; ra[t][1] = a1;                                           \
    }                                                                           \
} while (0)
#define ISSUEB(buf, ch) do {                                                    \
    uint32_t base = smb + (uint32_t)(buf) * 24576;                              \
    int r = tid >> 2, cc = tid & 3;                                             \
    uint32_t o = swo(r, cc);                                                    \
    size_t go = (size_t)r * S_ + (ch) * 32 + cc * 8;                            \
    CPA16(base + 16384 + o, Bh_ + go);                                          \
    CPA16(base + 20480 + o, Bl_ + go);                                          \
    CPA_COMMIT();                                                               \
} while (0)
#define STSA(buf) do {                                                          \
    char* bs = sm + (buf) * 24576;                                              \
    _Pragma("unroll")                                                           \
    for (int t = 0; t < 2; t++) {                                               \
        int id = tid + t * 256; int r = id >> 2, cc = id & 3;                   \
        uint32_t o = swo(r, cc);                                                \
        uint32_t h0,l0,h1,l1,h2,l2,h3,l3;                                       \
        split2(ra[t][0].x, ra[t][0].y, h0, l0);                                 \
        split2(ra[t][0].z, ra[t][0].w, h1, l1);                                 \
        split2(ra[t][1].x, ra[t][1].y, h2, l2);                                 \
        split2(ra[t][1].z, ra[t][1].w, h3, l3);                                 \
        *(uint4*)(bs + o)        = make_uint4(h0, h1, h2, h3);                  \
        *(uint4*)(bs + 8192 + o) = make_uint4(l0, l1, l2, l3);                  \
    }                                                                           \
} while (0)

    // Prologue: fill stages 0 and 1
    LOADA(0);       STSA(0); ISSUEB(0, 0);
    LOADA(32);      STSA(1); ISSUEB(1, 1);

    int buf = 0;
    for (int ch = 0; ch < NC; ch++) {
        if (ch + 1 < NC) { CPA_WAIT(1); } else { CPA_WAIT(0); }
        __syncthreads();
        if (ch + 2 < NC) LOADA((ch + 2) * 32);     // LDG early, hide under MMA
        const uint32_t bb = smb + (uint32_t)buf * 24576;
        MMA_BLOCK(4, bb, 8192, bb + 16384, 4096);
        if (ch + 2 < NC) {
            int nbuf = buf + 2; if (nbuf >= 3) nbuf -= 3;
            STSA(nbuf);
            ISSUEB(nbuf, ch + 2);
        }
        if (++buf == 3) buf = 0;
    }
#undef LOADA
#undef ISSUEB
#undef STSA

    // Epilogue -> ctx bf16 pairs
    const int b2 = bh >> 4, h = bh & 15;
    const int mr0 = m0 + wm * 32 + (lane >> 2);
    const int nl0 = wn * 32 + 2 * (lane & 3);
    #pragma unroll
    for (int i = 0; i < 2; i++)
        #pragma unroll
        for (int j = 0; j < 4; j++) {
            int n_loc = nl0 + j * 8;
            #pragma unroll
            for (int half = 0; half < 2; half++) {
                int m = mr0 + i * 16 + half * 8;
                size_t off = ((size_t)(b2 * S_ + m)) * D_ + h * DK + n_loc;
                st_pair(g_ctxh, g_ctxl, off, c[i][j][half*2+0], c[i][j][half*2+1]);
            }
        }
}

extern "C" void kernel_launch(void* const* d_in, const int* in_sizes, int n_in,
                              void* d_out, int out_size)
{
    (void)in_sizes; (void)n_in; (void)out_size;
    const float* query = (const float*)d_in[0];
    const float* key_  = (const float*)d_in[1];
    const float* value = (const float*)d_in[2];
    const float* Wq = (const float*)d_in[3];
    const float* bq = (const float*)d_in[4];
    const float* Wk = (const float*)d_in[5];
    const float* bk = (const float*)d_in[6];
    const float* Wv = (const float*)d_in[7];
    const float* bv = (const float*)d_in[8];
    const float* Wo = (const float*)d_in[9];
    const float* bo = (const float*)d_in[10];

    float* out  = (float*)d_out;
    float* attn = out + OUT_OFF;

    cudaFuncSetAttribute(gemm_ps<0>, cudaFuncAttributeMaxDynamicSharedMemorySize, 98304);
    cudaFuncSetAttribute(gemm_ps<1>, cudaFuncAttributeMaxDynamicSharedMemorySize, 98304);
    cudaFuncSetAttribute(scores_mma, cudaFuncAttributeMaxDynamicSharedMemorySize, 65536);
    cudaFuncSetAttribute(av_mma,     cudaFuncAttributeMaxDynamicSharedMemorySize, 73728);

    // One-time pre-split / transpose passes
    wt4_transpose_kernel<<<dim3(32, 32, 4), dim3(32, 8)>>>(Wq, Wk, Wv, Wo);
    split3_kernel<<<dim3(MR*D_/1024, 3), 256>>>(query, key_, value);

    // QKV projections (merged; sel = blockIdx.z)
    gemm_ps<0><<<dim3(8, 32, 3), 256, 98304>>>(bq, bk, bv, nullptr);

    // V^T hi/lo per head
    vt_transpose_kernel<<<dim3(2, 64, 32), dim3(32, 8)>>>();

    // Scores (e-values + stats) -> merge -> AV (fixup by FMUL, writes final P)
    scores_mma<<<dim3(16, 16, 32), 256, 65536>>>(attn);
    merge_stats<<<BH * S_ / 256, 256>>>();
    av_mma<<<dim3(1, 16, 32), 256, 73728>>>(attn);
    gemm_ps<1><<<dim3(8, 32), 256, 98304>>>(bo, nullptr, nullptr, out);
}

// round 17
// speedup vs baseline: 1.1594x; 1.1594x over previous
#include <cuda_runtime.h>
#include <cuda_bf16.h>
#include <stdint.h>

// Problem constants
#define S_ 2048
#define D_ 1024
#define HN 16
#define DK 64
#define BH 32
#define MR 4096                      // B*S
#define OUT_OFF ((size_t)MR*D_)      // start of attention_weights in d_out

// Scratch (device globals — referenced ONLY in device code)
__device__ float g_v[BH*S_*DK];                    // [bh][s][dk] fp32 (pre-transpose)
__device__ __nv_bfloat16 g_qh[BH*S_*DK], g_ql[BH*S_*DK];   // [bh][s][dk]
__device__ __nv_bfloat16 g_kh[BH*S_*DK], g_kl[BH*S_*DK];
__device__ __nv_bfloat16 g_vth[BH*DK*S_], g_vtl[BH*DK*S_]; // [bh][dk][s]
__device__ __nv_bfloat16 g_xh[(size_t)3*MR*D_], g_xl[(size_t)3*MR*D_];   // split inputs
__device__ __nv_bfloat16 g_wth[(size_t)4*D_*D_], g_wtl[(size_t)4*D_*D_]; // W^T hi/lo
__device__ __nv_bfloat16 g_ctxh[(size_t)MR*D_], g_ctxl[(size_t)MR*D_];

// ---------------------------------------------------------------------------
// Helpers
// ---------------------------------------------------------------------------
__device__ __forceinline__ uint32_t smem_u32(const void* p) {
    uint32_t a;
    asm("{ .reg .u64 t; cvta.to.shared.u64 t, %1; cvt.u32.u64 %0, t; }" : "=r"(a) : "l"(p));
    return a;
}
__device__ __forceinline__ void ldmx4(uint32_t& r0, uint32_t& r1, uint32_t& r2,
                                      uint32_t& r3, uint32_t addr) {
    asm volatile("ldmatrix.sync.aligned.m8n8.x4.shared.b16 {%0,%1,%2,%3}, [%4];"
                 : "=r"(r0), "=r"(r1), "=r"(r2), "=r"(r3) : "r"(addr));
}
__device__ __forceinline__ void mma16816(float* c, const uint32_t* a, const uint32_t* b) {
    asm volatile("mma.sync.aligned.m16n8k16.row.col.f32.bf16.bf16.f32 "
                 "{%0,%1,%2,%3}, {%4,%5,%6,%7}, {%8,%9}, {%0,%1,%2,%3};"
                 : "+f"(c[0]), "+f"(c[1]), "+f"(c[2]), "+f"(c[3])
                 : "r"(a[0]), "r"(a[1]), "r"(a[2]), "r"(a[3]), "r"(b[0]), "r"(b[1]));
}
#define CPA16(dst, src) \
    asm volatile("cp.async.cg.shared.global [%0], [%1], 16;" :: "r"(dst), "l"(src) : "memory")
#define CPA_COMMIT() asm volatile("cp.async.commit_group;" ::: "memory")
#define CPA_WAIT(n)  asm volatile("cp.async.wait_group %0;" :: "n"(n) : "memory")

// Split two fp32 into packed-bf16x2 (hi) and packed-bf16x2 residual (lo)
__device__ __forceinline__ void split2(float x, float y, uint32_t& hi, uint32_t& lo) {
    __nv_bfloat162 h2 = __float22bfloat162_rn(make_float2(x, y));
    uint32_t hb = *reinterpret_cast<uint32_t*>(&h2);
    float hx = __uint_as_float(hb << 16);
    float hy = __uint_as_float(hb & 0xFFFF0000u);
    __nv_bfloat162 l2 = __float22bfloat162_rn(make_float2(x - hx, y - hy));
    hi = hb;
    lo = *reinterpret_cast<uint32_t*>(&l2);
}
__device__ __forceinline__ void st_pair(__nv_bfloat16* dh, __nv_bfloat16* dl,
                                        size_t off, float v0, float v1) {
    uint32_t h, l; split2(v0, v1, h, l);
    *(uint32_t*)(dh + off) = h;
    *(uint32_t*)(dl + off) = l;
}
// Swizzled byte offset within a [rows x 32 bf16] region (64B rows, 16B chunks)
__device__ __forceinline__ uint32_t swo(int r, int cc) {
    return (uint32_t)(r * 64 + ((cc ^ ((r >> 1) & 3)) * 16));
}

// ---------------------------------------------------------------------------
// Merged elementwise split: grid (MR*D_/1024, 3); slot = blockIdx.y
// ---------------------------------------------------------------------------
__global__ void split3_kernel(const float* __restrict__ s0,
                              const float* __restrict__ s1,
                              const float* __restrict__ s2)
{
    int slot = blockIdx.y;
    const float* src = slot == 0 ? s0 : slot == 1 ? s1 : s2;
    __nv_bfloat16* dh = g_xh + (size_t)slot * MR * D_;
    __nv_bfloat16* dl = g_xl + (size_t)slot * MR * D_;
    size_t i = ((size_t)blockIdx.x * blockDim.x + threadIdx.x) * 4;
    float4 v = *(const float4*)(src + i);
    uint32_t h0, l0, h1, l1;
    split2(v.x, v.y, h0, l0);
    split2(v.z, v.w, h1, l1);
    *(uint2*)(dh + i) = make_uint2(h0, h1);
    *(uint2*)(dl + i) = make_uint2(l0, l1);
}

// ---------------------------------------------------------------------------
// Merged weight transpose+split: grid (32,32,4); dsel = blockIdx.z
// ---------------------------------------------------------------------------
__global__ void wt4_transpose_kernel(const float* __restrict__ w0,
                                     const float* __restrict__ w1,
                                     const float* __restrict__ w2,
                                     const float* __restrict__ w3)
{
    __shared__ float t[32][33];
    int dsel = blockIdx.z;
    const float* s = dsel == 0 ? w0 : dsel == 1 ? w1 : dsel == 2 ? w2 : w3;
    __nv_bfloat16* oh = g_wth + (size_t)dsel * D_ * D_;
    __nv_bfloat16* ol = g_wtl + (size_t)dsel * D_ * D_;
    int r0 = blockIdx.y * 32, c0 = blockIdx.x * 32;
    int x = threadIdx.x, y = threadIdx.y;
    #pragma unroll
    for (int i = 0; i < 32; i += 8)
        t[y + i][x] = s[(size_t)(r0 + y + i) * D_ + c0 + x];
    __syncthreads();
    #pragma unroll
    for (int i = 0; i < 32; i += 8) {
        float v = t[x][y + i];
        __nv_bfloat16 hb = __float2bfloat16(v);
        float r = v - __bfloat162float(hb);
        size_t o = (size_t)(c0 + y + i) * D_ + r0 + x;
        oh[o] = hb;
        ol[o] = __float2bfloat16(r);
    }
}

// ---------------------------------------------------------------------------
// V transpose+split per head: g_vt*[bh][dk][s] = split(g_v[bh][s][dk])
// grid (DK/32, S_/32, BH), block (32,8)
// ---------------------------------------------------------------------------
__global__ void vt_transpose_kernel()
{
    __shared__ float t[32][33];
    const float* s = g_v + (size_t)blockIdx.z * S_ * DK;
    __nv_bfloat16* oh = g_vth + (size_t)blockIdx.z * DK * S_;
    __nv_bfloat16* ol = g_vtl + (size_t)blockIdx.z * DK * S_;
    int r0 = blockIdx.y * 32, c0 = blockIdx.x * 32;
    int x = threadIdx.x, y = threadIdx.y;
    #pragma unroll
    for (int i = 0; i < 32; i += 8)
        t[y + i][x] = s[(size_t)(r0 + y + i) * DK + c0 + x];
    __syncthreads();
    #pragma unroll
    for (int i = 0; i < 32; i += 8) {
        float v = t[x][y + i];
        __nv_bfloat16 hb = __float2bfloat16(v);
        float r = v - __bfloat162float(hb);
        size_t o = (size_t)(c0 + y + i) * S_ + r0 + x;
        oh[o] = hb;
        ol[o] = __float2bfloat16(r);
    }
}

// ---------------------------------------------------------------------------
// MMA block: NT n-tiles/warp. A-hi at bbA, A-lo at bbA+ALO.
// B-hi at bbB, B-lo at bbB+BLO. Accumulates into c[2][NT][4].
// ---------------------------------------------------------------------------
#define MMA_BLOCK(NT, bbA, ALO, bbB, BLO)                                       \
    do {                                                                        \
        _Pragma("unroll")                                                       \
        for (int ks = 0; ks < 2; ks++) {                                        \
            uint32_t ah[2][4], al[2][4], bhf[NT][2], blf[NT][2];                \
            const int cc = ks * 2 + (lane >> 4);                                \
            _Pragma("unroll")                                                   \
            for (int i = 0; i < 2; i++) {                                       \
                int r = wm * 32 + i * 16 + (lane & 15);                         \
                uint32_t o = swo(r, cc);                                        \
                ldmx4(ah[i][0], ah[i][1], ah[i][2], ah[i][3], (bbA) + o);       \
                ldmx4(al[i][0], al[i][1], al[i][2], al[i][3], (bbA) + (ALO) + o);\
            }                                                                   \
            _Pragma("unroll")                                                   \
            for (int g = 0; g < NT / 2; g++) {                                  \
                int r = wn * (NT * 8) + g * 16 + (lane & 15);                   \
                uint32_t o = swo(r, cc);                                        \
                uint32_t t0, t1, t2, t3;                                        \
                ldmx4(t0, t1, t2, t3, (bbB) + o);                               \
                bhf[2*g][0] = t0; bhf[2*g+1][0] = t1;                           \
                bhf[2*g][1] = t2; bhf[2*g+1][1] = t3;                           \
                ldmx4(t0, t1, t2, t3, (bbB) + (BLO) + o);                       \
                blf[2*g][0] = t0; blf[2*g+1][0] = t1;                           \
                blf[2*g][1] = t2; blf[2*g+1][1] = t3;                           \
            }                                                                   \
            _Pragma("unroll")                                                   \
            for (int i = 0; i < 2; i++)                                         \
                _Pragma("unroll")                                               \
                for (int j = 0; j < NT; j++) {                                  \
                    mma16816(c[i][j], ah[i], bhf[j]);                           \
                    mma16816(c[i][j], ah[i], blf[j]);                           \
                    mma16816(c[i][j], al[i], bhf[j]);                           \
                }                                                               \
        }                                                                       \
    } while (0)

// ---------------------------------------------------------------------------
// gemm_ps<MODE>: pre-split A,B (bf16 hi/lo, LD=1024, K=1024), tile 128x128.
// MODE 0: sel=blockIdx.z: A=g_x[sel], B=g_wt[sel] -> q/k bf16 pairs or v fp32
// MODE 1: A=g_ctx, B=g_wt[3] -> d_out fp32 + bias
// smem: 3 stages x 32KB {AH 8K | AL 8K | BH 8K | BL 8K}; 1 sync/chunk
// __launch_bounds__(256,2): cap regs at 128 so 2 CTAs/SM co-reside (192KB smem)
// ---------------------------------------------------------------------------
template <int MODE>
__global__ __launch_bounds__(256, 2)
void gemm_ps(const float* __restrict__ b0, const float* __restrict__ b1,
             const float* __restrict__ b2, float* __restrict__ Cext)
{
    constexpr int NC = 32;
    extern __shared__ char sm[];
    const uint32_t smb = smem_u32(sm);
    const int tid = threadIdx.x, lane = tid & 31, wid = tid >> 5;
    const int wm = wid & 3, wn = wid >> 2;
    const int m0 = blockIdx.y * 128;
    const int n0 = blockIdx.x * 128;
    const int sel = (MODE == 0) ? blockIdx.z : 3;
    const float* bias = (MODE == 0) ? (sel == 0 ? b0 : sel == 1 ? b1 : b2) : b0;

    const __nv_bfloat16 *Ah, *Al, *Bh, *Bl;
    if (MODE == 0) {
        Ah = g_xh + (size_t)sel * MR * D_;  Al = g_xl + (size_t)sel * MR * D_;
    } else {
        Ah = g_ctxh;                        Al = g_ctxl;
    }
    Bh = g_wth + (size_t)sel * D_ * D_;     Bl = g_wtl + (size_t)sel * D_ * D_;
    Ah += (size_t)m0 * D_; Al += (size_t)m0 * D_;
    Bh += (size_t)n0 * D_; Bl += (size_t)n0 * D_;

    float c[2][8][4] = {};

#define ISSUE_PS(buf, ch) do {                                                  \
    uint32_t base = smb + (uint32_t)(buf) * 32768;                              \
    int k0 = (ch) * 32;                                                         \
    _Pragma("unroll")                                                           \
    for (int t = 0; t < 2; t++) {                                               \
        int id = tid + t * 256; int r = id >> 2, cc = id & 3;                   \
        uint32_t o = swo(r, cc);                                                \
        size_t go = (size_t)r * D_ + k0 + cc * 8;                               \
        CPA16(base + o,         Ah + go);                                       \
        CPA16(base + 8192 + o,  Al + go);                                       \
        CPA16(base + 16384 + o, Bh + go);                                       \
        CPA16(base + 24576 + o, Bl + go);                                       \
    }                                                                           \
    CPA_COMMIT();                                                               \
} while (0)

    ISSUE_PS(0, 0);
    ISSUE_PS(1, 1);
    int buf = 0;
    for (int ch = 0; ch < NC; ch++) {
        if (ch + 1 < NC) { CPA_WAIT(1); } else { CPA_WAIT(0); }
        __syncthreads();
        const uint32_t bb = smb + (uint32_t)buf * 32768;
        MMA_BLOCK(8, bb, 8192, bb + 16384, 8192);
        if (ch + 2 < NC) {
            int nbuf = buf + 2; if (nbuf >= 3) nbuf -= 3;
            ISSUE_PS(nbuf, ch + 2);
        }
        if (++buf == 3) buf = 0;
    }
#undef ISSUE_PS

    // Epilogue
    const int mr0 = m0 + wm * 32 + (lane >> 2);
    const int nl0 = wn * 64 + 2 * (lane & 3);
    #pragma unroll
    for (int i = 0; i < 2; i++)
        #pragma unroll
        for (int j = 0; j < 8; j++) {
            int n_loc = nl0 + j * 8;
            int ng = n0 + n_loc;
            float2 bv = *(const float2*)(bias + ng);
            #pragma unroll
            for (int half = 0; half < 2; half++) {
                int m = mr0 + i * 16 + half * 8;
                float v0 = c[i][j][half * 2 + 0] + bv.x;
                float v1 = c[i][j][half * 2 + 1] + bv.y;
                if constexpr (MODE == 0) {
                    int h = ng >> 6, d = ng & 63;
                    int b2_ = m >> 11, s = m & (S_ - 1);
                    size_t off = (((size_t)(b2_ * HN + h)) * S_ + s) * DK + d;
                    if (sel == 0)      st_pair(g_qh, g_ql, off, v0, v1);
                    else if (sel == 1) st_pair(g_kh, g_kl, off, v0, v1);
                    else               *(float2*)(g_v + off) = make_float2(v0, v1);
                } else {
                    *(float2*)(Cext + (size_t)m * D_ + ng) = make_float2(v0, v1);
                }
            }
        }
}

// ---------------------------------------------------------------------------
// scores: 0.125 * Q K^T per head, K=64 single shot, tile 128x128.
// smem 64KB: QH [2 chunks x 8K] | QL +16384 | KH +32768 | KL +49152
// ---------------------------------------------------------------------------
__global__ __launch_bounds__(256, 2)
void scores_mma(float* __restrict__ attn)
{
    extern __shared__ char sm[];
    const uint32_t smb = smem_u32(sm);
    const int tid = threadIdx.x, lane = tid & 31, wid = tid >> 5;
    const int wm = wid & 3, wn = wid >> 2;
    const int m0 = blockIdx.y * 128;
    const int n0 = blockIdx.x * 128;
    const int bh = blockIdx.z;

    const __nv_bfloat16* Qh = g_qh + ((size_t)bh * S_ + m0) * DK;
    const __nv_bfloat16* Ql = g_ql + ((size_t)bh * S_ + m0) * DK;
    const __nv_bfloat16* Kh = g_kh + ((size_t)bh * S_ + n0) * DK;
    const __nv_bfloat16* Kl = g_kl + ((size_t)bh * S_ + n0) * DK;

    #pragma unroll
    for (int t = 0; t < 4; t++) {
        int id = tid + t * 256;
        int ch = id >> 9, r = (id >> 2) & 127, cc = id & 3;
        uint32_t o = (uint32_t)ch * 8192 + swo(r, cc);
        size_t go = (size_t)r * DK + ch * 32 + cc * 8;
        CPA16(smb + o,         Qh + go);
        CPA16(smb + 16384 + o, Ql + go);
        CPA16(smb + 32768 + o, Kh + go);
        CPA16(smb + 49152 + o, Kl + go);
    }
    CPA_COMMIT();
    CPA_WAIT(0);
    __syncthreads();

    float c[2][8][4] = {};
    #pragma unroll
    for (int chk = 0; chk < 2; chk++) {
        const uint32_t bb = smb + (uint32_t)chk * 8192;
        MMA_BLOCK(8, bb, 16384, bb + 32768, 16384);
    }

    const int mr0 = m0 + wm * 32 + (lane >> 2);
    const int nl0 = wn * 64 + 2 * (lane & 3);
    float* C = attn + (size_t)bh * S_ * S_;
    #pragma unroll
    for (int i = 0; i < 2; i++)
        #pragma unroll
        for (int j = 0; j < 8; j++) {
            int ng = n0 + nl0 + j * 8;
            #pragma unroll
            for (int half = 0; half < 2; half++) {
                int m = mr0 + i * 16 + half * 8;
                *(float2*)(C + (size_t)m * S_ + ng) =
                    make_float2(c[i][j][half*2+0] * 0.125f, c[i][j][half*2+1] * 0.125f);
            }
        }
}

// ---------------------------------------------------------------------------
// av: ctx = attn @ V. A = fp32 attn (in-kernel split), B = pre-split V^T.
// tile 128x64, K=2048, NC=64. smem 3 stages x 24KB {AH|AL|BH|BL}; 1 sync/chunk
// ---------------------------------------------------------------------------
__global__ __launch_bounds__(256, 2)
void av_mma(const float* __restrict__ attn)
{
    constexpr int NC = 64;
    extern __shared__ char sm[];
    const uint32_t smb = smem_u32(sm);
    const int tid = threadIdx.x, lane = tid & 31, wid = tid >> 5;
    const int wm = wid & 3, wn = wid >> 2;
    const int m0 = blockIdx.y * 128;
    const int bh = blockIdx.z;

    const float* Ap = attn + (size_t)bh * S_ * S_ + (size_t)m0 * S_;
    const __nv_bfloat16* Bh_ = g_vth + (size_t)bh * DK * S_;
    const __nv_bfloat16* Bl_ = g_vtl + (size_t)bh * DK * S_;

    float c[2][4][4] = {};
    float4 ra[2][2];

#define LOADA(k0) do {                                                          \
    _Pragma("unroll")                                                           \
    for (int t = 0; t < 2; t++) {                                               \
        int id = tid + t * 256; int r = id >> 2, cc = id & 3;                   \
        const float* p = Ap + (size_t)r * S_ + (k0) + cc * 8;                   \
        ra[t][0] = *(const float4*)p; ra[t][1] = *(const float4*)(p + 4);       \
    }                                                                           \
} while (0)
#define ISSUEB(buf, ch) do {                                                    \
    uint32_t base = smb + (uint32_t)(buf) * 24576;                              \
    int r = tid >> 2, cc = tid & 3;                                             \
    uint32_t o = swo(r, cc);                                                    \
    size_t go = (size_t)r * S_ + (ch) * 32 + cc * 8;                            \
    CPA16(base + 16384 + o, Bh_ + go);                                          \
    CPA16(base + 20480 + o, Bl_ + go);                                          \
    CPA_COMMIT();                                                               \
} while (0)
#define STSA(buf) do {                                                          \
    char* bs = sm + (buf) * 24576;                                              \
    _Pragma("unroll")                                                           \
    for (int t = 0; t < 2; t++) {                                               \
        int id = tid + t * 256; int r = id >> 2, cc = id & 3;                   \
        uint32_t o = swo(r, cc);                                                \
        uint32_t h0,l0,h1,l1,h2,l2,h3,l3;                                       \
        split2(ra[t][0].x, ra[t][0].y, h0, l0);                                 \
        split2(ra[t][0].z, ra[t][0].w, h1, l1);                                 \
        split2(ra[t][1].x, ra[t][1].y, h2, l2);                                 \
        split2(ra[t][1].z, ra[t][1].w, h3, l3);                                 \
        *(uint4*)(bs + o)        = make_uint4(h0, h1, h2, h3);                  \
        *(uint4*)(bs + 8192 + o) = make_uint4(l0, l1, l2, l3);                  \
    }                                                                           \
} while (0)

    // Prologue: fill stages 0 and 1
    LOADA(0);       STSA(0); ISSUEB(0, 0);
    LOADA(32);      STSA(1); ISSUEB(1, 1);

    int buf = 0;
    for (int ch = 0; ch < NC; ch++) {
        if (ch + 1 < NC) { CPA_WAIT(1); } else { CPA_WAIT(0); }
        __syncthreads();
        if (ch + 2 < NC) LOADA((ch + 2) * 32);     // LDG early, hide under MMA
        const uint32_t bb = smb + (uint32_t)buf * 24576;
        MMA_BLOCK(4, bb, 8192, bb + 16384, 4096);
        if (ch + 2 < NC) {
            int nbuf = buf + 2; if (nbuf >= 3) nbuf -= 3;
            STSA(nbuf);
            ISSUEB(nbuf, ch + 2);
        }
        if (++buf == 3) buf = 0;
    }
#undef LOADA
#undef ISSUEB
#undef STSA

    // Epilogue -> ctx bf16 pairs
    const int b2 = bh >> 4, h = bh & 15;
    const int mr0 = m0 + wm * 32 + (lane >> 2);
    const int nl0 = wn * 32 + 2 * (lane & 3);
    #pragma unroll
    for (int i = 0; i < 2; i++)
        #pragma unroll
        for (int j = 0; j < 4; j++) {
            int n_loc = nl0 + j * 8;
            #pragma unroll
            for (int half = 0; half < 2; half++) {
                int m = mr0 + i * 16 + half * 8;
                size_t off = ((size_t)(b2 * S_ + m)) * D_ + h * DK + n_loc;
                st_pair(g_ctxh, g_ctxl, off, c[i][j][half*2+0], c[i][j][half*2+1]);
            }
        }
}

// ---------------------------------------------------------------------------
// Row softmax in place over attn rows of length 2048. One block per row.
// ---------------------------------------------------------------------------
__global__ void softmax_kernel(float* __restrict__ attn)
{
    const size_t row = blockIdx.x;
    float* p = attn + row * (size_t)S_;
    const int tid = threadIdx.x;
    const int lane = tid & 31, wid = tid >> 5;
    __shared__ float red[8];

    float4 v0 = ((const float4*)p)[tid];
    float4 v1 = ((const float4*)p)[tid + 256];

    float m = fmaxf(fmaxf(fmaxf(v0.x, v0.y), fmaxf(v0.z, v0.w)),
                    fmaxf(fmaxf(v1.x, v1.y), fmaxf(v1.z, v1.w)));
    #pragma unroll
    for (int o = 16; o; o >>= 1) m = fmaxf(m, __shfl_xor_sync(0xffffffffu, m, o));
    if (lane == 0) red[wid] = m;
    __syncthreads();
    if (tid == 0) {
        float mm = red[0];
        #pragma unroll
        for (int i = 1; i < 8; i++) mm = fmaxf(mm, red[i]);
        red[0] = mm;
    }
    __syncthreads();
    m = red[0];
    __syncthreads();

    float4 e0, e1;
    e0.x = __expf(v0.x - m); e0.y = __expf(v0.y - m);
    e0.z = __expf(v0.z - m); e0.w = __expf(v0.w - m);
    e1.x = __expf(v1.x - m); e1.y = __expf(v1.y - m);
    e1.z = __expf(v1.z - m); e1.w = __expf(v1.w - m);

    float s = (e0.x + e0.y + e0.z + e0.w) + (e1.x + e1.y + e1.z + e1.w);
    #pragma unroll
    for (int o = 16; o; o >>= 1) s += __shfl_xor_sync(0xffffffffu, s, o);
    if (lane == 0) red[wid] = s;
    __syncthreads();
    if (tid == 0) {
        float ss = 0.f;
        #pragma unroll
        for (int i = 0; i < 8; i++) ss += red[i];
        red[0] = ss;
    }
    __syncthreads();
    float inv = 1.0f / red[0];

    e0.x *= inv; e0.y *= inv; e0.z *= inv; e0.w *= inv;
    e1.x *= inv; e1.y *= inv; e1.z *= inv; e1.w *= inv;
    ((float4*)p)[tid] = e0;
    ((float4*)p)[tid + 256] = e1;
}

extern "C" void kernel_launch(void* const* d_in, const int* in_sizes, int n_in,
                              void* d_out, int out_size)
{
    (void)in_sizes; (void)n_in; (void)out_size;
    const float* query = (const float*)d_in[0];
    const float* key_  = (const float*)d_in[1];
    const float* value = (const float*)d_in[2];
    const float* Wq = (const float*)d_in[3];
    const float* bq = (const float*)d_in[4];
    const float* Wk = (const float*)d_in[5];
    const float* bk = (const float*)d_in[6];
    const float* Wv = (const float*)d_in[7];
    const float* bv = (const float*)d_in[8];
    const float* Wo = (const float*)d_in[9];
    const float* bo = (const float*)d_in[10];

    float* out  = (float*)d_out;
    float* attn = out + OUT_OFF;

    cudaFuncSetAttribute(gemm_ps<0>, cudaFuncAttributeMaxDynamicSharedMemorySize, 98304);
    cudaFuncSetAttribute(gemm_ps<1>, cudaFuncAttributeMaxDynamicSharedMemorySize, 98304);
    cudaFuncSetAttribute(scores_mma, cudaFuncAttributeMaxDynamicSharedMemorySize, 65536);
    cudaFuncSetAttribute(av_mma,     cudaFuncAttributeMaxDynamicSharedMemorySize, 73728);

    // One-time pre-split / transpose passes
    wt4_transpose_kernel<<<dim3(32, 32, 4), dim3(32, 8)>>>(Wq, Wk, Wv, Wo);
    split3_kernel<<<dim3(MR*D_/1024, 3), 256>>>(query, key_, value);

    // QKV projections (merged; sel = blockIdx.z)
    gemm_ps<0><<<dim3(8, 32, 3), 256, 98304>>>(bq, bk, bv, nullptr);

    // V^T hi/lo per head
    vt_transpose_kernel<<<dim3(2, 64, 32), dim3(32, 8)>>>();

    // Scores, softmax, AV, output projection
    scores_mma<<<dim3(16, 16, 32), 256, 65536>>>(attn);
    softmax_kernel<<<BH * S_, 256>>>(attn);
    av_mma<<<dim3(1, 16, 32), 256, 73728>>>(attn);
    gemm_ps<1><<<dim3(8, 32), 256, 98304>>>(bo, nullptr, nullptr, out);
}